// round 14
// baseline (speedup 1.0000x reference)
#include <cuda_runtime.h>
#include <cuda_bf16.h>
#include <cstdint>
#include <math.h>

// Problem constants
#define BB 4
#define TT 2048
#define DD 1024
#define HH 16
#define HS 64
#define MROWS (BB*TT)          // 8192
#define D3 (3*DD)              // 3072
#define D4 (4*DD)              // 4096

typedef __nv_bfloat16 bf16;

// ---------------- scratch (device globals; no allocs allowed) ----------------
__device__ bf16 g_hh [MROWS*DD], g_hl [MROWS*DD];     // LN1 out pair
__device__ bf16 g_oh [MROWS*DD], g_ol [MROWS*DD];     // attention out pair
__device__ bf16 g_x2h[MROWS*DD], g_x2l[MROWS*DD];     // h + proj pair
__device__ bf16 g_h2h[MROWS*DD], g_h2l[MROWS*DD];     // LN2 out pair
__device__ bf16 g_mdh[MROWS*D4], g_mdl[MROWS*D4];     // FFN hidden pair
__device__ bf16 g_qkv_h[MROWS*D3], g_qkv_l[MROWS*D3]; // qkv pair
// bf16 hi/lo weights, [N][K] layout
__device__ bf16 g_Wqkv_h[D3*DD], g_Wqkv_l[D3*DD];
__device__ bf16 g_Wp_h [DD*DD], g_Wp_l [DD*DD];
__device__ bf16 g_W1_h [D4*DD], g_W1_l [D4*DD];
__device__ bf16 g_W2_h [DD*D4], g_W2_l [DD*D4];

// ======================= small PTX helpers ===================================
__device__ __forceinline__ uint32_t smem_u32(const void* p) {
    uint32_t a;
    asm("{ .reg .u64 t; cvta.to.shared.u64 t, %1; cvt.u32.u64 %0, t; }" : "=r"(a) : "l"(p));
    return a;
}
__device__ __forceinline__ void ldm4(uint32_t* r, uint32_t addr) {
    asm volatile("ldmatrix.sync.aligned.m8n8.x4.shared.b16 {%0,%1,%2,%3}, [%4];"
        : "=r"(r[0]), "=r"(r[1]), "=r"(r[2]), "=r"(r[3]) : "r"(addr));
}
__device__ __forceinline__ void ldm4t(uint32_t* r, uint32_t addr) {
    asm volatile("ldmatrix.sync.aligned.m8n8.x4.trans.shared.b16 {%0,%1,%2,%3}, [%4];"
        : "=r"(r[0]), "=r"(r[1]), "=r"(r[2]), "=r"(r[3]) : "r"(addr));
}
__device__ __forceinline__ void mma16816(float* d, const uint32_t* a, const uint32_t* b) {
    asm volatile("mma.sync.aligned.m16n8k16.row.col.f32.bf16.bf16.f32 "
        "{%0,%1,%2,%3}, {%4,%5,%6,%7}, {%8,%9}, {%0,%1,%2,%3};"
        : "+f"(d[0]), "+f"(d[1]), "+f"(d[2]), "+f"(d[3])
        : "r"(a[0]), "r"(a[1]), "r"(a[2]), "r"(a[3]), "r"(b[0]), "r"(b[1]));
}
__device__ __forceinline__ uint32_t pack_bf16(float a, float b) {
    bf16 x = __float2bfloat16(a), y = __float2bfloat16(b);
    return ((uint32_t)__bfloat16_as_ushort(y) << 16) | __bfloat16_as_ushort(x);
}
__device__ __forceinline__ void split2(float a, float b, uint32_t& hp, uint32_t& lp) {
    bf16 h0 = __float2bfloat16(a), h1 = __float2bfloat16(b);
    hp = ((uint32_t)__bfloat16_as_ushort(h1) << 16) | __bfloat16_as_ushort(h0);
    lp = pack_bf16(a - __bfloat162float(h0), b - __bfloat162float(h1));
}
__device__ __forceinline__ void cpa16(uint32_t dst, const void* src) {
    asm volatile("cp.async.cg.shared.global [%0], [%1], 16;" :: "r"(dst), "l"(src));
}
#define CP_COMMIT() asm volatile("cp.async.commit_group;" ::: "memory")
#define CP_WAIT1()  asm volatile("cp.async.wait_group 1;" ::: "memory")
#define CP_WAIT0()  asm volatile("cp.async.wait_group 0;" ::: "memory")

// swizzled smem address for 64B rows: q16 = col16 ^ ((row>>1)&3)
__device__ __forceinline__ uint32_t swz64(uint32_t base, int row, int colByte) {
    int c16 = colByte >> 4;
    int q = c16 ^ ((row >> 1) & 3);
    return base + (uint32_t)(row * 64 + (q << 4));
}
// swizzled smem address for 128B rows: q16 = col16 ^ (row&7)
__device__ __forceinline__ uint32_t swz128(uint32_t base, int row, int colByte) {
    int c16 = colByte >> 4;
    int q = c16 ^ (row & 7);
    return base + (uint32_t)(row * 128 + (q << 4));
}

// ======== weight prep: transpose W[K][N] -> out[N][K] bf16 hi/lo =============
__global__ void prep_tr(const float* __restrict__ W,
                        bf16* __restrict__ oh, bf16* __restrict__ ol, int K, int N) {
    __shared__ float ts[32][33];
    int n0 = blockIdx.x * 32, k0 = blockIdx.y * 32;
    int tx = threadIdx.x, ty = threadIdx.y;     // (32,8)
    #pragma unroll
    for (int i = 0; i < 4; i++)
        ts[ty + 8*i][tx] = W[(size_t)(k0 + ty + 8*i) * N + n0 + tx];
    __syncthreads();
    #pragma unroll
    for (int i = 0; i < 4; i++) {
        float v = ts[tx][ty + 8*i];
        size_t o = (size_t)(n0 + ty + 8*i) * K + k0 + tx;
        bf16 h = __float2bfloat16(v);
        oh[o] = h;
        ol[o] = __float2bfloat16(v - __bfloat162float(h));
    }
}

// QKV weights: Wq/Wk/Wv [H][D][HS] -> out[n=(sec,h,hs)][k=d] bf16 hi/lo
__global__ void prep_qkv(const float* __restrict__ Wq, const float* __restrict__ Wk,
                         const float* __restrict__ Wv,
                         bf16* __restrict__ oh, bf16* __restrict__ ol) {
    __shared__ float ts[32][33];
    int hs0 = blockIdx.x * 32;
    int d0  = blockIdx.y * 32;
    int z   = blockIdx.z;
    int sec = z >> 4, hh = z & 15;
    const float* W = (sec == 0) ? Wq : (sec == 1) ? Wk : Wv;
    int tx = threadIdx.x, ty = threadIdx.y;
    #pragma unroll
    for (int i = 0; i < 4; i++)
        ts[ty + 8*i][tx] = W[(size_t)hh * (DD*HS) + (size_t)(d0 + ty + 8*i) * HS + hs0 + tx];
    __syncthreads();
    #pragma unroll
    for (int i = 0; i < 4; i++) {
        float v = ts[tx][ty + 8*i];
        int n = sec * 1024 + hh * 64 + hs0 + ty + 8*i;
        size_t o = (size_t)n * DD + d0 + tx;
        bf16 h = __float2bfloat16(v);
        oh[o] = h;
        ol[o] = __float2bfloat16(v - __bfloat162float(h));
    }
}

// ---------------- LayerNorm: fp32 or pair input -> pair output ---------------
template <bool PAIRIN>
__global__ void ln_kernel(const float* __restrict__ x,
                          const bf16* __restrict__ xh, const bf16* __restrict__ xl,
                          const float* __restrict__ g, const float* __restrict__ b,
                          bf16* __restrict__ yh, bf16* __restrict__ yl) {
    int row = blockIdx.x;
    int tid = threadIdx.x;
    float4 v;
    if (PAIRIN) {
        const uint2 hv = *(const uint2*)(xh + (size_t)row * DD + tid * 4);
        const uint2 lv = *(const uint2*)(xl + (size_t)row * DD + tid * 4);
        __nv_bfloat162 h0 = *(const __nv_bfloat162*)&hv.x;
        __nv_bfloat162 h1 = *(const __nv_bfloat162*)&hv.y;
        __nv_bfloat162 l0 = *(const __nv_bfloat162*)&lv.x;
        __nv_bfloat162 l1 = *(const __nv_bfloat162*)&lv.y;
        v.x = __bfloat162float(h0.x) + __bfloat162float(l0.x);
        v.y = __bfloat162float(h0.y) + __bfloat162float(l0.y);
        v.z = __bfloat162float(h1.x) + __bfloat162float(l1.x);
        v.w = __bfloat162float(h1.y) + __bfloat162float(l1.y);
    } else {
        v = *(const float4*)(x + (size_t)row * DD + tid * 4);
    }
    float s  = v.x + v.y + v.z + v.w;
    float sq = v.x*v.x + v.y*v.y + v.z*v.z + v.w*v.w;
    #pragma unroll
    for (int o = 16; o > 0; o >>= 1) {
        s  += __shfl_xor_sync(0xffffffffu, s,  o);
        sq += __shfl_xor_sync(0xffffffffu, sq, o);
    }
    __shared__ float ws[8], wq[8];
    int wid = tid >> 5, lid = tid & 31;
    if (lid == 0) { ws[wid] = s; wq[wid] = sq; }
    __syncthreads();
    if (wid == 0) {
        float a = (lid < 8) ? ws[lid] : 0.f;
        float c = (lid < 8) ? wq[lid] : 0.f;
        #pragma unroll
        for (int o = 4; o > 0; o >>= 1) {
            a += __shfl_xor_sync(0xffffffffu, a, o);
            c += __shfl_xor_sync(0xffffffffu, c, o);
        }
        if (lid == 0) { ws[0] = a; wq[0] = c; }
    }
    __syncthreads();
    float mu  = ws[0] * (1.0f / DD);
    float var = wq[0] * (1.0f / DD) - mu * mu;
    float inv = rsqrtf(var + 1e-5f);
    const float4 gg = *(const float4*)(g + tid * 4);
    const float4 bb = *(const float4*)(b + tid * 4);
    float o0 = (v.x - mu) * inv * gg.x + bb.x;
    float o1 = (v.y - mu) * inv * gg.y + bb.y;
    float o2 = (v.z - mu) * inv * gg.z + bb.z;
    float o3 = (v.w - mu) * inv * gg.w + bb.w;
    uint2 hp, lp;
    split2(o0, o1, hp.x, lp.x);
    split2(o2, o3, hp.y, lp.y);
    *(uint2*)(yh + (size_t)row * DD + tid * 4) = hp;
    *(uint2*)(yl + (size_t)row * DD + tid * 4) = lp;
}

// ============ persistent mma.sync GEMM ======================================
// C[M,N] = (Ah+Al)[M,K] @ (Bh+Bl)[N,K]^T, 3-term split-bf16, fp32 accum.
// Fixed grid (2 CTAs/SM), each CTA loops over 128x128 tiles with a
// continuously-rotating 3-stage cp.async ring pipelined ACROSS tiles.
#define TILE_BYTES (128*64)            // 8192 (swizzled, no pad)
#define STAGE_BYTES (4*TILE_BYTES)     // Ah, Al, Bh, Bl = 32768
#define GEMM_SMEM (3*STAGE_BYTES)      // 98304
#define GEMM_GRID 296

template <bool RELU, bool EMITBF>
__global__ __launch_bounds__(256, 2)
void gemm_tc(const bf16* __restrict__ Ah, const bf16* __restrict__ Al,
             const bf16* __restrict__ Bh, const bf16* __restrict__ Bl,
             const float* __restrict__ bias,
             const bf16* __restrict__ resh, const bf16* __restrict__ resl,
             float* __restrict__ C, bf16* __restrict__ Oh, bf16* __restrict__ Ol,
             int M, int N, int K) {
    extern __shared__ char smem[];
    uint32_t sb = smem_u32(smem);
    int tid = threadIdx.x, wid = tid >> 5, lane = tid & 31;
    int wm = wid >> 1, wn = wid & 1;

    // loader coords: 4 threads per row, 16B (8 elems) each
    int lrow = tid >> 2, lq = tid & 3;
    uint32_t so0 = (uint32_t)(lrow * 64 + ((lq ^ ((lrow >> 1) & 3)) << 4));
    uint32_t so1 = so0 + 64 * 64;
    const size_t half = (size_t)64 * K;
    const int lcol = lq * 8;

    const int nch = K >> 5;
    const int nbx = N >> 7;                     // tiles along N
    const int ntiles = (M >> 7) * nbx;
    const int stride = (int)gridDim.x;

    // load one 32-wide K-chunk of tile (m0,n0) into stage st3
    auto load_chunk = [&](int m0, int n0, int c, int st3) {
        uint32_t st = sb + (uint32_t)st3 * STAGE_BYTES;
        int koff = c * 32 + lcol;
        const bf16* A0h = Ah + (size_t)(m0 + lrow) * K + koff;
        const bf16* A0l = Al + (size_t)(m0 + lrow) * K + koff;
        const bf16* B0h = Bh + (size_t)(n0 + lrow) * K + koff;
        const bf16* B0l = Bl + (size_t)(n0 + lrow) * K + koff;
        cpa16(st + 0*TILE_BYTES + so0, A0h);
        cpa16(st + 0*TILE_BYTES + so1, A0h + half);
        cpa16(st + 1*TILE_BYTES + so0, A0l);
        cpa16(st + 1*TILE_BYTES + so1, A0l + half);
        cpa16(st + 2*TILE_BYTES + so0, B0h);
        cpa16(st + 2*TILE_BYTES + so1, B0h + half);
        cpa16(st + 3*TILE_BYTES + so0, B0l);
        cpa16(st + 3*TILE_BYTES + so1, B0l + half);
        CP_COMMIT();
    };

    int a_r = ((lane >> 3) & 1) * 8 + (lane & 7);
    int a_c = (lane >> 4) * 8;
    int b_r = (lane >> 4) * 8 + (lane & 7);
    int b_c = ((lane >> 3) & 1) * 8;
    int trow = lane >> 2, tcol = (lane & 3) * 2;

    int t0 = (int)blockIdx.x;
    int g = 0, gcommit = 0;                     // global chunk / committed counters
    if (t0 < ntiles) {
        int m0 = (t0 / nbx) * 128, n0 = (t0 % nbx) * 128;
        load_chunk(m0, n0, 0, 0);
        load_chunk(m0, n0, 1, 1);
        gcommit = 2;
    }

    for (int t = t0; t < ntiles; t += stride) {
        int m0 = (t / nbx) * 128, n0 = (t % nbx) * 128;
        int tn = t + stride;
        int mn0 = 0, nn0 = 0;
        if (tn < ntiles) { mn0 = (tn / nbx) * 128; nn0 = (tn % nbx) * 128; }

        float acc[2][8][4];
        #pragma unroll
        for (int i = 0; i < 2; i++)
            #pragma unroll
            for (int j = 0; j < 8; j++)
                #pragma unroll
                for (int q = 0; q < 4; q++) acc[i][j][q] = 0.f;

        for (int c = 0; c < nch; c++, g++) {
            if (gcommit - g >= 2) CP_WAIT1();
            else                  CP_WAIT0();
            __syncthreads();
            if (c + 2 < nch)      { load_chunk(m0, n0, c + 2, gcommit % 3); gcommit++; }
            else if (tn < ntiles) { load_chunk(mn0, nn0, c + 2 - nch, gcommit % 3); gcommit++; }
            uint32_t stage = sb + (uint32_t)(g % 3) * STAGE_BYTES;
            #pragma unroll
            for (int k16 = 0; k16 < 32; k16 += 16) {
                uint32_t ah[2][4], al[2][4];
                #pragma unroll
                for (int mt = 0; mt < 2; mt++) {
                    int row = wm*32 + mt*16 + a_r;
                    int cb  = (k16 + a_c) * 2;
                    ldm4(ah[mt], swz64(stage + 0*TILE_BYTES, row, cb));
                    ldm4(al[mt], swz64(stage + 1*TILE_BYTES, row, cb));
                }
                #pragma unroll
                for (int nt = 0; nt < 4; nt++) {
                    uint32_t bh[4], bl[4];
                    int row = wn*64 + nt*16 + b_r;
                    int cb  = (k16 + b_c) * 2;
                    ldm4(bh, swz64(stage + 2*TILE_BYTES, row, cb));
                    ldm4(bl, swz64(stage + 3*TILE_BYTES, row, cb));
                    mma16816(acc[0][2*nt+0], ah[0], bh + 0);
                    mma16816(acc[1][2*nt+0], ah[1], bh + 0);
                    mma16816(acc[0][2*nt+1], ah[0], bh + 2);
                    mma16816(acc[1][2*nt+1], ah[1], bh + 2);
                    mma16816(acc[0][2*nt+0], al[0], bh + 0);
                    mma16816(acc[1][2*nt+0], al[1], bh + 0);
                    mma16816(acc[0][2*nt+1], al[0], bh + 2);
                    mma16816(acc[1][2*nt+1], al[1], bh + 2);
                    mma16816(acc[0][2*nt+0], ah[0], bl + 0);
                    mma16816(acc[1][2*nt+0], ah[1], bl + 0);
                    mma16816(acc[0][2*nt+1], ah[0], bl + 2);
                    mma16816(acc[1][2*nt+1], ah[1], bl + 2);
                }
            }
        }

        // ---- epilogue (overlaps the next tile's in-flight cp.asyncs) ----
        #pragma unroll
        for (int mt = 0; mt < 2; mt++) {
            #pragma unroll
            for (int rr = 0; rr < 2; rr++) {
                int row = m0 + wm*32 + mt*16 + rr*8 + trow;
                #pragma unroll
                for (int j = 0; j < 8; j++) {
                    int col = n0 + wn*64 + j*8 + tcol;
                    float v0 = acc[mt][j][rr*2+0];
                    float v1 = acc[mt][j][rr*2+1];
                    if (bias) { v0 += bias[col]; v1 += bias[col+1]; }
                    if (RELU) { v0 = fmaxf(v0, 0.f); v1 = fmaxf(v1, 0.f); }
                    if (resh) {
                        uint32_t rh = *(const uint32_t*)(resh + (size_t)row * N + col);
                        uint32_t rl = *(const uint32_t*)(resl + (size_t)row * N + col);
                        __nv_bfloat162 h2v = *(const __nv_bfloat162*)&rh;
                        __nv_bfloat162 l2v = *(const __nv_bfloat162*)&rl;
                        v0 += __bfloat162float(h2v.x) + __bfloat162float(l2v.x);
                        v1 += __bfloat162float(h2v.y) + __bfloat162float(l2v.y);
                    }
                    if (EMITBF) {
                        uint32_t hp, lp;
                        split2(v0, v1, hp, lp);
                        *(uint32_t*)(Oh + (size_t)row * N + col) = hp;
                        *(uint32_t*)(Ol + (size_t)row * N + col) = lp;
                    } else {
                        float2 o2; o2.x = v0; o2.y = v1;
                        *(float2*)(C + (size_t)row * N + col) = o2;
                    }
                }
            }
        }
    }
}

// ============ Tensor-core causal flash attention (unchanged from R13) =======
#define ATILE_B (64*128)                     // 8192 per matrix tile
#define ASTAGE_B (4*ATILE_B)                 // Kh,Kl,Vh,Vl = 32768
#define ATTN_SMEM3 (3*ASTAGE_B)              // 98304

__global__ __launch_bounds__(256, 2)
void attn_tc(const bf16* __restrict__ qh, const bf16* __restrict__ ql,
             bf16* __restrict__ oh, bf16* __restrict__ ol) {
    extern __shared__ char smem[];
    uint32_t sb = smem_u32(smem);
    int tid = threadIdx.x, w = tid >> 5, lane = tid & 31;
    int qb = (int)(gridDim.x - 1 - blockIdx.x);
    int b  = blockIdx.y >> 4, h = blockIdx.y & 15;
    int wrow  = qb * 128 + w * 16;
    int trow = lane >> 2, tc2 = (lane & 3) * 2;
    int gr0 = wrow + trow, gr1 = gr0 + 8;

    uint32_t Qh[4][4], Ql[4][4];
    {
        size_t r0 = ((size_t)b * TT + gr0) * D3 + h * 64;
        size_t r1 = ((size_t)b * TT + gr1) * D3 + h * 64;
        #pragma unroll
        for (int ks = 0; ks < 4; ks++) {
            int c0 = ks * 16 + tc2;
            Qh[ks][0] = *(const uint32_t*)(qh + r0 + c0);
            Qh[ks][1] = *(const uint32_t*)(qh + r1 + c0);
            Qh[ks][2] = *(const uint32_t*)(qh + r0 + c0 + 8);
            Qh[ks][3] = *(const uint32_t*)(qh + r1 + c0 + 8);
            Ql[ks][0] = *(const uint32_t*)(ql + r0 + c0);
            Ql[ks][1] = *(const uint32_t*)(ql + r1 + c0);
            Ql[ks][2] = *(const uint32_t*)(ql + r0 + c0 + 8);
            Ql[ks][3] = *(const uint32_t*)(ql + r1 + c0 + 8);
        }
    }

    float oacc[8][4];
    #pragma unroll
    for (int j = 0; j < 8; j++)
        #pragma unroll
        for (int q = 0; q < 4; q++) oacc[j][q] = 0.f;
    float m0 = -1e30f, m1 = -1e30f, l0 = 0.f, l1 = 0.f;

    const int nkt = 2 * qb + 2;
    size_t kcol = 1024 + h * 64;
    size_t vcol = 2048 + h * 64;

    auto load_tile = [&](int kt) {
        uint32_t st = sb + (uint32_t)(kt % 3) * ASTAGE_B;
        #pragma unroll
        for (int i = 0; i < 2; i++) {
            int o = tid + i * 256;
            int row = o >> 3, seg = o & 7;
            size_t gbase = ((size_t)b * TT + kt * 64 + row) * D3 + seg * 8;
            uint32_t soff = (uint32_t)(row * 128 + ((seg ^ (row & 7)) << 4));
            cpa16(st + 0*ATILE_B + soff, qh + gbase + kcol);
            cpa16(st + 1*ATILE_B + soff, ql + gbase + kcol);
            cpa16(st + 2*ATILE_B + soff, qh + gbase + vcol);
            cpa16(st + 3*ATILE_B + soff, ql + gbase + vcol);
        }
        CP_COMMIT();
    };

    int kb_r = (lane >> 4) * 8 + (lane & 7);
    int kb_c = ((lane >> 3) & 1) * 8;
    int vb_r = ((lane >> 3) & 1) * 8 + (lane & 7);
    int vb_c = (lane >> 4) * 8;

    load_tile(0);
    if (nkt > 1) load_tile(1);
    for (int kt = 0; kt < nkt; kt++) {
        if (kt + 1 < nkt) CP_WAIT1();
        else              CP_WAIT0();
        __syncthreads();
        if (kt + 2 < nkt) load_tile(kt + 2);
        uint32_t stage = sb + (uint32_t)(kt % 3) * ASTAGE_B;
        int kbkey = kt * 64;

        float sacc[8][4];
        #pragma unroll
        for (int j = 0; j < 8; j++)
            #pragma unroll
            for (int q = 0; q < 4; q++) sacc[j][q] = 0.f;
        #pragma unroll
        for (int ks = 0; ks < 4; ks++) {
            #pragma unroll
            for (int ng = 0; ng < 4; ng++) {
                uint32_t kh[4], kl[4];
                int row = ng*16 + kb_r;
                int cb  = (ks*16 + kb_c) * 2;
                ldm4(kh, swz128(stage + 0*ATILE_B, row, cb));
                ldm4(kl, swz128(stage + 1*ATILE_B, row, cb));
                mma16816(sacc[2*ng+0], Qh[ks], kh + 0);
                mma16816(sacc[2*ng+1], Qh[ks], kh + 2);
                mma16816(sacc[2*ng+0], Ql[ks], kh + 0);
                mma16816(sacc[2*ng+1], Ql[ks], kh + 2);
                mma16816(sacc[2*ng+0], Qh[ks], kl + 0);
                mma16816(sacc[2*ng+1], Qh[ks], kl + 2);
            }
        }
        const float scale = 0.03125f;
        #pragma unroll
        for (int j = 0; j < 8; j++)
            #pragma unroll
            for (int q = 0; q < 4; q++) sacc[j][q] *= scale;
        if (kbkey + 63 > wrow) {
            #pragma unroll
            for (int j = 0; j < 8; j++) {
                int c0 = kbkey + j*8 + tc2;
                if (c0     > gr0) sacc[j][0] = -1e30f;
                if (c0 + 1 > gr0) sacc[j][1] = -1e30f;
                if (c0     > gr1) sacc[j][2] = -1e30f;
                if (c0 + 1 > gr1) sacc[j][3] = -1e30f;
            }
        }
        float mt0 = -1e30f, mt1 = -1e30f;
        #pragma unroll
        for (int j = 0; j < 8; j++) {
            mt0 = fmaxf(mt0, fmaxf(sacc[j][0], sacc[j][1]));
            mt1 = fmaxf(mt1, fmaxf(sacc[j][2], sacc[j][3]));
        }
        mt0 = fmaxf(mt0, __shfl_xor_sync(0xffffffffu, mt0, 1));
        mt0 = fmaxf(mt0, __shfl_xor_sync(0xffffffffu, mt0, 2));
        mt1 = fmaxf(mt1, __shfl_xor_sync(0xffffffffu, mt1, 1));
        mt1 = fmaxf(mt1, __shfl_xor_sync(0xffffffffu, mt1, 2));
        float mn0 = fmaxf(m0, mt0), mn1 = fmaxf(m1, mt1);
        float f0 = __expf(m0 - mn0), f1 = __expf(m1 - mn1);
        float rs0 = 0.f, rs1 = 0.f;
        #pragma unroll
        for (int j = 0; j < 8; j++) {
            sacc[j][0] = __expf(sacc[j][0] - mn0);
            sacc[j][1] = __expf(sacc[j][1] - mn0);
            sacc[j][2] = __expf(sacc[j][2] - mn1);
            sacc[j][3] = __expf(sacc[j][3] - mn1);
            rs0 += sacc[j][0] + sacc[j][1];
            rs1 += sacc[j][2] + sacc[j][3];
        }
        rs0 += __shfl_xor_sync(0xffffffffu, rs0, 1);
        rs0 += __shfl_xor_sync(0xffffffffu, rs0, 2);
        rs1 += __shfl_xor_sync(0xffffffffu, rs1, 1);
        rs1 += __shfl_xor_sync(0xffffffffu, rs1, 2);
        l0 = l0 * f0 + rs0;  l1 = l1 * f1 + rs1;
        m0 = mn0;  m1 = mn1;
        #pragma unroll
        for (int j = 0; j < 8; j++) {
            oacc[j][0] *= f0; oacc[j][1] *= f0;
            oacc[j][2] *= f1; oacc[j][3] *= f1;
        }
        #pragma unroll
        for (int ks = 0; ks < 4; ks++) {
            uint32_t pfr[4];
            pfr[0] = pack_bf16(sacc[2*ks  ][0], sacc[2*ks  ][1]);
            pfr[1] = pack_bf16(sacc[2*ks  ][2], sacc[2*ks  ][3]);
            pfr[2] = pack_bf16(sacc[2*ks+1][0], sacc[2*ks+1][1]);
            pfr[3] = pack_bf16(sacc[2*ks+1][2], sacc[2*ks+1][3]);
            #pragma unroll
            for (int nd = 0; nd < 4; nd++) {
                uint32_t vh[4], vl[4];
                int row = ks*16 + vb_r;
                int cb  = (nd*16 + vb_c) * 2;
                ldm4t(vh, swz128(stage + 2*ATILE_B, row, cb));
                ldm4t(vl, swz128(stage + 3*ATILE_B, row, cb));
                mma16816(oacc[2*nd+0], pfr, vh + 0);
                mma16816(oacc[2*nd+1], pfr, vh + 2);
                mma16816(oacc[2*nd+0], pfr, vl + 0);
                mma16816(oacc[2*nd+1], pfr, vl + 2);
            }
        }
    }

    float rl0 = 1.0f / l0, rl1 = 1.0f / l1;
    size_t ob0 = ((size_t)b * TT + gr0) * DD + h * 64;
    size_t ob1 = ((size_t)b * TT + gr1) * DD + h * 64;
    #pragma unroll
    for (int jd = 0; jd < 8; jd++) {
        uint32_t hp, lp;
        split2(oacc[jd][0] * rl0, oacc[jd][1] * rl0, hp, lp);
        *(uint32_t*)(oh + ob0 + jd*8 + tc2) = hp;
        *(uint32_t*)(ol + ob0 + jd*8 + tc2) = lp;
        split2(oacc[jd][2] * rl1, oacc[jd][3] * rl1, hp, lp);
        *(uint32_t*)(oh + ob1 + jd*8 + tc2) = hp;
        *(uint32_t*)(ol + ob1 + jd*8 + tc2) = lp;
    }
}

// ---------------- launch ------------------------------------------------------
extern "C" void kernel_launch(void* const* d_in, const int* in_sizes, int n_in,
                              void* d_out, int out_size) {
    const float* x   = (const float*)d_in[0];
    const float* Wq  = (const float*)d_in[1];
    const float* Wk  = (const float*)d_in[2];
    const float* Wv  = (const float*)d_in[3];
    const float* Wp  = (const float*)d_in[4];
    const float* bp  = (const float*)d_in[5];
    const float* W1  = (const float*)d_in[6];
    const float* b1  = (const float*)d_in[7];
    const float* W2  = (const float*)d_in[8];
    const float* b2  = (const float*)d_in[9];
    const float* g1  = (const float*)d_in[10];
    const float* be1 = (const float*)d_in[11];
    const float* g2  = (const float*)d_in[12];
    const float* be2 = (const float*)d_in[13];
    float* out = (float*)d_out;

    bf16 *hh, *hl, *oh, *ol, *x2h, *x2l, *h2h, *h2l, *mdh, *mdl, *qkvh, *qkvl;
    cudaGetSymbolAddress((void**)&hh,  g_hh);  cudaGetSymbolAddress((void**)&hl,  g_hl);
    cudaGetSymbolAddress((void**)&oh,  g_oh);  cudaGetSymbolAddress((void**)&ol,  g_ol);
    cudaGetSymbolAddress((void**)&x2h, g_x2h); cudaGetSymbolAddress((void**)&x2l, g_x2l);
    cudaGetSymbolAddress((void**)&h2h, g_h2h); cudaGetSymbolAddress((void**)&h2l, g_h2l);
    cudaGetSymbolAddress((void**)&mdh, g_mdh); cudaGetSymbolAddress((void**)&mdl, g_mdl);
    cudaGetSymbolAddress((void**)&qkvh, g_qkv_h); cudaGetSymbolAddress((void**)&qkvl, g_qkv_l);
    bf16 *Wqkv_h, *Wqkv_l, *Wp_h, *Wp_l, *W1_h, *W1_l, *W2_h, *W2_l;
    cudaGetSymbolAddress((void**)&Wqkv_h, g_Wqkv_h);
    cudaGetSymbolAddress((void**)&Wqkv_l, g_Wqkv_l);
    cudaGetSymbolAddress((void**)&Wp_h, g_Wp_h);
    cudaGetSymbolAddress((void**)&Wp_l, g_Wp_l);
    cudaGetSymbolAddress((void**)&W1_h, g_W1_h);
    cudaGetSymbolAddress((void**)&W1_l, g_W1_l);
    cudaGetSymbolAddress((void**)&W2_h, g_W2_h);
    cudaGetSymbolAddress((void**)&W2_l, g_W2_l);

    cudaFuncSetAttribute(attn_tc,
                         cudaFuncAttributeMaxDynamicSharedMemorySize, ATTN_SMEM3);
    cudaFuncSetAttribute(gemm_tc<false,true>,
                         cudaFuncAttributeMaxDynamicSharedMemorySize, GEMM_SMEM);
    cudaFuncSetAttribute(gemm_tc<true,true>,
                         cudaFuncAttributeMaxDynamicSharedMemorySize, GEMM_SMEM);
    cudaFuncSetAttribute(gemm_tc<false,false>,
                         cudaFuncAttributeMaxDynamicSharedMemorySize, GEMM_SMEM);

    dim3 tb(32, 8);
    prep_qkv<<<dim3(2, 32, 48), tb>>>(Wq, Wk, Wv, Wqkv_h, Wqkv_l);
    prep_tr<<<dim3(DD/32, DD/32), tb>>>(Wp, Wp_h, Wp_l, DD, DD);
    prep_tr<<<dim3(D4/32, DD/32), tb>>>(W1, W1_h, W1_l, DD, D4);
    prep_tr<<<dim3(DD/32, D4/32), tb>>>(W2, W2_h, W2_l, D4, DD);

    // LN1 (fp32 in, pair out)
    ln_kernel<false><<<MROWS, 256>>>(x, nullptr, nullptr, g1, be1, hh, hl);
    // QKV GEMM -> qkv pair
    gemm_tc<false,true><<<GEMM_GRID, 256, GEMM_SMEM>>>(
        hh, hl, Wqkv_h, Wqkv_l, nullptr, nullptr, nullptr,
        nullptr, qkvh, qkvl, MROWS, D3, DD);
    // attention -> o pair
    attn_tc<<<dim3(TT/128, BB*HH), 256, ATTN_SMEM3>>>(qkvh, qkvl, oh, ol);
    // proj + bias + residual(h) -> x2 pair
    gemm_tc<false,true><<<GEMM_GRID, 256, GEMM_SMEM>>>(
        oh, ol, Wp_h, Wp_l, bp, hh, hl,
        nullptr, x2h, x2l, MROWS, DD, DD);
    // LN2 (pair in, pair out)
    ln_kernel<true><<<MROWS, 256>>>(nullptr, x2h, x2l, g2, be2, h2h, h2l);
    // FFN1 + bias + relu -> mid pair
    gemm_tc<true,true><<<GEMM_GRID, 256, GEMM_SMEM>>>(
        h2h, h2l, W1_h, W1_l, b1, nullptr, nullptr,
        nullptr, mdh, mdl, MROWS, D4, DD);
    // FFN2 + bias + residual(h2) -> fp32 out
    gemm_tc<false,false><<<GEMM_GRID, 256, GEMM_SMEM>>>(
        mdh, mdl, W2_h, W2_l, b2, h2h, h2l,
        out, nullptr, nullptr, MROWS, DD, D4);
}

// round 16
// speedup vs baseline: 1.0603x; 1.0603x over previous
#include <cuda_runtime.h>
#include <cuda_bf16.h>
#include <cstdint>
#include <math.h>

// Problem constants
#define BB 4
#define TT 2048
#define DD 1024
#define HH 16
#define HS 64
#define MROWS (BB*TT)          // 8192
#define D3 (3*DD)              // 3072
#define D4 (4*DD)              // 4096

typedef __nv_bfloat16 bf16;

// ---------------- scratch (device globals; no allocs allowed) ----------------
__device__ bf16 g_hh [MROWS*DD], g_hl [MROWS*DD];     // LN1 out pair
__device__ bf16 g_oh [MROWS*DD], g_ol [MROWS*DD];     // attention out pair
__device__ bf16 g_x2h[MROWS*DD], g_x2l[MROWS*DD];     // h + proj pair
__device__ bf16 g_h2h[MROWS*DD], g_h2l[MROWS*DD];     // LN2 out pair
__device__ bf16 g_mdh[MROWS*D4], g_mdl[MROWS*D4];     // FFN hidden pair
__device__ bf16 g_qkv_h[MROWS*D3], g_qkv_l[MROWS*D3]; // qkv pair
// bf16 hi/lo weights, [N][K] layout
__device__ bf16 g_Wqkv_h[D3*DD], g_Wqkv_l[D3*DD];
__device__ bf16 g_Wp_h [DD*DD], g_Wp_l [DD*DD];
__device__ bf16 g_W1_h [D4*DD], g_W1_l [D4*DD];
__device__ bf16 g_W2_h [DD*D4], g_W2_l [DD*D4];

// ======================= small PTX helpers ===================================
__device__ __forceinline__ uint32_t smem_u32(const void* p) {
    uint32_t a;
    asm("{ .reg .u64 t; cvta.to.shared.u64 t, %1; cvt.u32.u64 %0, t; }" : "=r"(a) : "l"(p));
    return a;
}
__device__ __forceinline__ void ldm4(uint32_t* r, uint32_t addr) {
    asm volatile("ldmatrix.sync.aligned.m8n8.x4.shared.b16 {%0,%1,%2,%3}, [%4];"
        : "=r"(r[0]), "=r"(r[1]), "=r"(r[2]), "=r"(r[3]) : "r"(addr));
}
__device__ __forceinline__ void ldm4t(uint32_t* r, uint32_t addr) {
    asm volatile("ldmatrix.sync.aligned.m8n8.x4.trans.shared.b16 {%0,%1,%2,%3}, [%4];"
        : "=r"(r[0]), "=r"(r[1]), "=r"(r[2]), "=r"(r[3]) : "r"(addr));
}
__device__ __forceinline__ void mma16816(float* d, const uint32_t* a, const uint32_t* b) {
    asm volatile("mma.sync.aligned.m16n8k16.row.col.f32.bf16.bf16.f32 "
        "{%0,%1,%2,%3}, {%4,%5,%6,%7}, {%8,%9}, {%0,%1,%2,%3};"
        : "+f"(d[0]), "+f"(d[1]), "+f"(d[2]), "+f"(d[3])
        : "r"(a[0]), "r"(a[1]), "r"(a[2]), "r"(a[3]), "r"(b[0]), "r"(b[1]));
}
__device__ __forceinline__ uint32_t pack_bf16(float a, float b) {
    bf16 x = __float2bfloat16(a), y = __float2bfloat16(b);
    return ((uint32_t)__bfloat16_as_ushort(y) << 16) | __bfloat16_as_ushort(x);
}
__device__ __forceinline__ void split2(float a, float b, uint32_t& hp, uint32_t& lp) {
    bf16 h0 = __float2bfloat16(a), h1 = __float2bfloat16(b);
    hp = ((uint32_t)__bfloat16_as_ushort(h1) << 16) | __bfloat16_as_ushort(h0);
    lp = pack_bf16(a - __bfloat162float(h0), b - __bfloat162float(h1));
}
__device__ __forceinline__ void cpa16(uint32_t dst, const void* src) {
    asm volatile("cp.async.cg.shared.global [%0], [%1], 16;" :: "r"(dst), "l"(src));
}
#define CP_COMMIT() asm volatile("cp.async.commit_group;" ::: "memory")
#define CP_WAIT1()  asm volatile("cp.async.wait_group 1;" ::: "memory")
#define CP_WAIT0()  asm volatile("cp.async.wait_group 0;" ::: "memory")

// swizzled smem address for 64B rows: q16 = col16 ^ ((row>>1)&3)
__device__ __forceinline__ uint32_t swz64(uint32_t base, int row, int colByte) {
    int c16 = colByte >> 4;
    int q = c16 ^ ((row >> 1) & 3);
    return base + (uint32_t)(row * 64 + (q << 4));
}
// swizzled smem address for 128B rows: q16 = col16 ^ (row&7)
__device__ __forceinline__ uint32_t swz128(uint32_t base, int row, int colByte) {
    int c16 = colByte >> 4;
    int q = c16 ^ (row & 7);
    return base + (uint32_t)(row * 128 + (q << 4));
}

// ======== fused weight prep: Wp, W1, W2 transpose -> [N][K] bf16 hi/lo =======
// block decode: [0,1024) Wp (nb=32), [1024,5120) W1 (nb=128), [5120,9216) W2 (nb=32)
__global__ void prep_all(const float* __restrict__ Wp,
                         const float* __restrict__ W1,
                         const float* __restrict__ W2) {
    __shared__ float ts[32][33];
    int idx = blockIdx.x;
    const float* W; bf16 *oh, *ol; int K, N, nb;
    if (idx < 1024)      { W = Wp;            oh = g_Wp_h; ol = g_Wp_l; K = DD; N = DD; nb = 32; }
    else if (idx < 5120) { W = W1; idx -= 1024; oh = g_W1_h; ol = g_W1_l; K = DD; N = D4; nb = 128; }
    else                 { W = W2; idx -= 5120; oh = g_W2_h; ol = g_W2_l; K = D4; N = DD; nb = 32; }
    int n0 = (idx % nb) * 32, k0 = (idx / nb) * 32;
    int tx = threadIdx.x, ty = threadIdx.y;     // (32,8)
    #pragma unroll
    for (int i = 0; i < 4; i++)
        ts[ty + 8*i][tx] = W[(size_t)(k0 + ty + 8*i) * N + n0 + tx];
    __syncthreads();
    #pragma unroll
    for (int i = 0; i < 4; i++) {
        float v = ts[tx][ty + 8*i];
        size_t o = (size_t)(n0 + ty + 8*i) * K + k0 + tx;
        bf16 h = __float2bfloat16(v);
        oh[o] = h;
        ol[o] = __float2bfloat16(v - __bfloat162float(h));
    }
}

// QKV weights: Wq/Wk/Wv [H][D][HS] -> out[n=(sec,h,hs)][k=d] bf16 hi/lo
__global__ void prep_qkv(const float* __restrict__ Wq, const float* __restrict__ Wk,
                         const float* __restrict__ Wv,
                         bf16* __restrict__ oh, bf16* __restrict__ ol) {
    __shared__ float ts[32][33];
    int hs0 = blockIdx.x * 32;
    int d0  = blockIdx.y * 32;
    int z   = blockIdx.z;
    int sec = z >> 4, hh = z & 15;
    const float* W = (sec == 0) ? Wq : (sec == 1) ? Wk : Wv;
    int tx = threadIdx.x, ty = threadIdx.y;
    #pragma unroll
    for (int i = 0; i < 4; i++)
        ts[ty + 8*i][tx] = W[(size_t)hh * (DD*HS) + (size_t)(d0 + ty + 8*i) * HS + hs0 + tx];
    __syncthreads();
    #pragma unroll
    for (int i = 0; i < 4; i++) {
        float v = ts[tx][ty + 8*i];
        int n = sec * 1024 + hh * 64 + hs0 + ty + 8*i;
        size_t o = (size_t)n * DD + d0 + tx;
        bf16 h = __float2bfloat16(v);
        oh[o] = h;
        ol[o] = __float2bfloat16(v - __bfloat162float(h));
    }
}

// ---------------- LayerNorm: fp32 or pair input -> pair output ---------------
template <bool PAIRIN>
__global__ void ln_kernel(const float* __restrict__ x,
                          const bf16* __restrict__ xh, const bf16* __restrict__ xl,
                          const float* __restrict__ g, const float* __restrict__ b,
                          bf16* __restrict__ yh, bf16* __restrict__ yl) {
    int row = blockIdx.x;
    int tid = threadIdx.x;
    float4 v;
    if (PAIRIN) {
        const uint2 hv = *(const uint2*)(xh + (size_t)row * DD + tid * 4);
        const uint2 lv = *(const uint2*)(xl + (size_t)row * DD + tid * 4);
        __nv_bfloat162 h0 = *(const __nv_bfloat162*)&hv.x;
        __nv_bfloat162 h1 = *(const __nv_bfloat162*)&hv.y;
        __nv_bfloat162 l0 = *(const __nv_bfloat162*)&lv.x;
        __nv_bfloat162 l1 = *(const __nv_bfloat162*)&lv.y;
        v.x = __bfloat162float(h0.x) + __bfloat162float(l0.x);
        v.y = __bfloat162float(h0.y) + __bfloat162float(l0.y);
        v.z = __bfloat162float(h1.x) + __bfloat162float(l1.x);
        v.w = __bfloat162float(h1.y) + __bfloat162float(l1.y);
    } else {
        v = *(const float4*)(x + (size_t)row * DD + tid * 4);
    }
    float s  = v.x + v.y + v.z + v.w;
    float sq = v.x*v.x + v.y*v.y + v.z*v.z + v.w*v.w;
    #pragma unroll
    for (int o = 16; o > 0; o >>= 1) {
        s  += __shfl_xor_sync(0xffffffffu, s,  o);
        sq += __shfl_xor_sync(0xffffffffu, sq, o);
    }
    __shared__ float ws[8], wq[8];
    int wid = tid >> 5, lid = tid & 31;
    if (lid == 0) { ws[wid] = s; wq[wid] = sq; }
    __syncthreads();
    if (wid == 0) {
        float a = (lid < 8) ? ws[lid] : 0.f;
        float c = (lid < 8) ? wq[lid] : 0.f;
        #pragma unroll
        for (int o = 4; o > 0; o >>= 1) {
            a += __shfl_xor_sync(0xffffffffu, a, o);
            c += __shfl_xor_sync(0xffffffffu, c, o);
        }
        if (lid == 0) { ws[0] = a; wq[0] = c; }
    }
    __syncthreads();
    float mu  = ws[0] * (1.0f / DD);
    float var = wq[0] * (1.0f / DD) - mu * mu;
    float inv = rsqrtf(var + 1e-5f);
    const float4 gg = *(const float4*)(g + tid * 4);
    const float4 bb = *(const float4*)(b + tid * 4);
    float o0 = (v.x - mu) * inv * gg.x + bb.x;
    float o1 = (v.y - mu) * inv * gg.y + bb.y;
    float o2 = (v.z - mu) * inv * gg.z + bb.z;
    float o3 = (v.w - mu) * inv * gg.w + bb.w;
    uint2 hp, lp;
    split2(o0, o1, hp.x, lp.x);
    split2(o2, o3, hp.y, lp.y);
    *(uint2*)(yh + (size_t)row * DD + tid * 4) = hp;
    *(uint2*)(yl + (size_t)row * DD + tid * 4) = lp;
}

// ============ mma.sync GEMM: C[M,N] = (Ah+Al)[M,K] @ (Bh+Bl)[N,K]^T ==========
// 3-term split-bf16 fp32 accum. cp.async 3-stage pipeline, swizzled 64B rows,
// ONE sync per chunk, 2 CTAs/SM. (R13-validated configuration)
#define TILE_BYTES (128*64)            // 8192 (swizzled, no pad)
#define STAGE_BYTES (4*TILE_BYTES)     // Ah, Al, Bh, Bl = 32768
#define GEMM_SMEM (3*STAGE_BYTES)      // 98304

template <bool RELU, bool EMITBF>
__global__ __launch_bounds__(256, 2)
void gemm_tc(const bf16* __restrict__ Ah, const bf16* __restrict__ Al,
             const bf16* __restrict__ Bh, const bf16* __restrict__ Bl,
             const float* __restrict__ bias,
             const bf16* __restrict__ resh, const bf16* __restrict__ resl,
             float* __restrict__ C, bf16* __restrict__ Oh, bf16* __restrict__ Ol,
             int M, int N, int K) {
    extern __shared__ char smem[];
    uint32_t sb = smem_u32(smem);
    int tid = threadIdx.x, wid = tid >> 5, lane = tid & 31;
    int wm = wid >> 1, wn = wid & 1;
    int m0 = blockIdx.y * 128, n0 = blockIdx.x * 128;

    // loader coords: 4 threads per row, 16B (8 elems) each
    int lrow = tid >> 2, lq = tid & 3;
    const bf16* pAh = Ah + (size_t)(m0 + lrow) * K + lq * 8;
    const bf16* pAl = Al + (size_t)(m0 + lrow) * K + lq * 8;
    const bf16* pBh = Bh + (size_t)(n0 + lrow) * K + lq * 8;
    const bf16* pBl = Bl + (size_t)(n0 + lrow) * K + lq * 8;
    uint32_t so0 = (uint32_t)(lrow * 64 + ((lq ^ ((lrow >> 1) & 3)) << 4));
    uint32_t so1 = so0 + 64 * 64;
    const size_t half = (size_t)64 * K;

    const int nch = K >> 5;

    auto load_chunk = [&](int c) {
        uint32_t st = sb + (uint32_t)(c % 3) * STAGE_BYTES;
        int koff = c * 32;
        cpa16(st + 0*TILE_BYTES + so0, pAh + koff);
        cpa16(st + 0*TILE_BYTES + so1, pAh + half + koff);
        cpa16(st + 1*TILE_BYTES + so0, pAl + koff);
        cpa16(st + 1*TILE_BYTES + so1, pAl + half + koff);
        cpa16(st + 2*TILE_BYTES + so0, pBh + koff);
        cpa16(st + 2*TILE_BYTES + so1, pBh + half + koff);
        cpa16(st + 3*TILE_BYTES + so0, pBl + koff);
        cpa16(st + 3*TILE_BYTES + so1, pBl + half + koff);
        CP_COMMIT();
    };

    float acc[2][8][4];
    #pragma unroll
    for (int i = 0; i < 2; i++)
        #pragma unroll
        for (int j = 0; j < 8; j++)
            #pragma unroll
            for (int q = 0; q < 4; q++) acc[i][j][q] = 0.f;

    int a_r = ((lane >> 3) & 1) * 8 + (lane & 7);
    int a_c = (lane >> 4) * 8;
    int b_r = (lane >> 4) * 8 + (lane & 7);
    int b_c = ((lane >> 3) & 1) * 8;

    load_chunk(0);
    load_chunk(1);
    for (int c = 0; c < nch; c++) {
        if (c + 1 < nch) CP_WAIT1();
        else             CP_WAIT0();
        __syncthreads();
        if (c + 2 < nch) load_chunk(c + 2);
        uint32_t stage = sb + (uint32_t)(c % 3) * STAGE_BYTES;
        #pragma unroll
        for (int k16 = 0; k16 < 32; k16 += 16) {
            uint32_t ah[2][4], al[2][4];
            #pragma unroll
            for (int mt = 0; mt < 2; mt++) {
                int row = wm*32 + mt*16 + a_r;
                int cb  = (k16 + a_c) * 2;
                ldm4(ah[mt], swz64(stage + 0*TILE_BYTES, row, cb));
                ldm4(al[mt], swz64(stage + 1*TILE_BYTES, row, cb));
            }
            #pragma unroll
            for (int nt = 0; nt < 4; nt++) {
                uint32_t bh[4], bl[4];
                int row = wn*64 + nt*16 + b_r;
                int cb  = (k16 + b_c) * 2;
                ldm4(bh, swz64(stage + 2*TILE_BYTES, row, cb));
                ldm4(bl, swz64(stage + 3*TILE_BYTES, row, cb));
                mma16816(acc[0][2*nt+0], ah[0], bh + 0);
                mma16816(acc[1][2*nt+0], ah[1], bh + 0);
                mma16816(acc[0][2*nt+1], ah[0], bh + 2);
                mma16816(acc[1][2*nt+1], ah[1], bh + 2);
                mma16816(acc[0][2*nt+0], al[0], bh + 0);
                mma16816(acc[1][2*nt+0], al[1], bh + 0);
                mma16816(acc[0][2*nt+1], al[0], bh + 2);
                mma16816(acc[1][2*nt+1], al[1], bh + 2);
                mma16816(acc[0][2*nt+0], ah[0], bl + 0);
                mma16816(acc[1][2*nt+0], ah[1], bl + 0);
                mma16816(acc[0][2*nt+1], ah[0], bl + 2);
                mma16816(acc[1][2*nt+1], ah[1], bl + 2);
            }
        }
    }

    // ---- epilogue ----
    int trow = lane >> 2, tcol = (lane & 3) * 2;
    #pragma unroll
    for (int mt = 0; mt < 2; mt++) {
        #pragma unroll
        for (int rr = 0; rr < 2; rr++) {
            int row = m0 + wm*32 + mt*16 + rr*8 + trow;
            #pragma unroll
            for (int j = 0; j < 8; j++) {
                int col = n0 + wn*64 + j*8 + tcol;
                float v0 = acc[mt][j][rr*2+0];
                float v1 = acc[mt][j][rr*2+1];
                if (bias) { v0 += bias[col]; v1 += bias[col+1]; }
                if (RELU) { v0 = fmaxf(v0, 0.f); v1 = fmaxf(v1, 0.f); }
                if (resh) {
                    uint32_t rh = *(const uint32_t*)(resh + (size_t)row * N + col);
                    uint32_t rl = *(const uint32_t*)(resl + (size_t)row * N + col);
                    __nv_bfloat162 h2v = *(const __nv_bfloat162*)&rh;
                    __nv_bfloat162 l2v = *(const __nv_bfloat162*)&rl;
                    v0 += __bfloat162float(h2v.x) + __bfloat162float(l2v.x);
                    v1 += __bfloat162float(h2v.y) + __bfloat162float(l2v.y);
                }
                if (EMITBF) {
                    uint32_t hp, lp;
                    split2(v0, v1, hp, lp);
                    *(uint32_t*)(Oh + (size_t)row * N + col) = hp;
                    *(uint32_t*)(Ol + (size_t)row * N + col) = lp;
                } else {
                    float2 o2; o2.x = v0; o2.y = v1;
                    *(float2*)(C + (size_t)row * N + col) = o2;
                }
            }
        }
    }
}

// ============ Tensor-core causal flash attention (R13 config) ================
#define ATILE_B (64*128)                     // 8192 per matrix tile
#define ASTAGE_B (4*ATILE_B)                 // Kh,Kl,Vh,Vl = 32768
#define ATTN_SMEM3 (3*ASTAGE_B)              // 98304

__global__ __launch_bounds__(256, 2)
void attn_tc(const bf16* __restrict__ qh, const bf16* __restrict__ ql,
             bf16* __restrict__ oh, bf16* __restrict__ ol) {
    extern __shared__ char smem[];
    uint32_t sb = smem_u32(smem);
    int tid = threadIdx.x, w = tid >> 5, lane = tid & 31;
    int qb = (int)(gridDim.x - 1 - blockIdx.x);
    int b  = blockIdx.y >> 4, h = blockIdx.y & 15;
    int wrow  = qb * 128 + w * 16;
    int trow = lane >> 2, tc2 = (lane & 3) * 2;
    int gr0 = wrow + trow, gr1 = gr0 + 8;

    uint32_t Qh[4][4], Ql[4][4];
    {
        size_t r0 = ((size_t)b * TT + gr0) * D3 + h * 64;
        size_t r1 = ((size_t)b * TT + gr1) * D3 + h * 64;
        #pragma unroll
        for (int ks = 0; ks < 4; ks++) {
            int c0 = ks * 16 + tc2;
            Qh[ks][0] = *(const uint32_t*)(qh + r0 + c0);
            Qh[ks][1] = *(const uint32_t*)(qh + r1 + c0);
            Qh[ks][2] = *(const uint32_t*)(qh + r0 + c0 + 8);
            Qh[ks][3] = *(const uint32_t*)(qh + r1 + c0 + 8);
            Ql[ks][0] = *(const uint32_t*)(ql + r0 + c0);
            Ql[ks][1] = *(const uint32_t*)(ql + r1 + c0);
            Ql[ks][2] = *(const uint32_t*)(ql + r0 + c0 + 8);
            Ql[ks][3] = *(const uint32_t*)(ql + r1 + c0 + 8);
        }
    }

    float oacc[8][4];
    #pragma unroll
    for (int j = 0; j < 8; j++)
        #pragma unroll
        for (int q = 0; q < 4; q++) oacc[j][q] = 0.f;
    float m0 = -1e30f, m1 = -1e30f, l0 = 0.f, l1 = 0.f;

    const int nkt = 2 * qb + 2;
    size_t kcol = 1024 + h * 64;
    size_t vcol = 2048 + h * 64;

    auto load_tile = [&](int kt) {
        uint32_t st = sb + (uint32_t)(kt % 3) * ASTAGE_B;
        #pragma unroll
        for (int i = 0; i < 2; i++) {
            int o = tid + i * 256;
            int row = o >> 3, seg = o & 7;
            size_t gbase = ((size_t)b * TT + kt * 64 + row) * D3 + seg * 8;
            uint32_t soff = (uint32_t)(row * 128 + ((seg ^ (row & 7)) << 4));
            cpa16(st + 0*ATILE_B + soff, qh + gbase + kcol);
            cpa16(st + 1*ATILE_B + soff, ql + gbase + kcol);
            cpa16(st + 2*ATILE_B + soff, qh + gbase + vcol);
            cpa16(st + 3*ATILE_B + soff, ql + gbase + vcol);
        }
        CP_COMMIT();
    };

    int kb_r = (lane >> 4) * 8 + (lane & 7);
    int kb_c = ((lane >> 3) & 1) * 8;
    int vb_r = ((lane >> 3) & 1) * 8 + (lane & 7);
    int vb_c = (lane >> 4) * 8;

    load_tile(0);
    if (nkt > 1) load_tile(1);
    for (int kt = 0; kt < nkt; kt++) {
        if (kt + 1 < nkt) CP_WAIT1();
        else              CP_WAIT0();
        __syncthreads();
        if (kt + 2 < nkt) load_tile(kt + 2);
        uint32_t stage = sb + (uint32_t)(kt % 3) * ASTAGE_B;
        int kbkey = kt * 64;

        float sacc[8][4];
        #pragma unroll
        for (int j = 0; j < 8; j++)
            #pragma unroll
            for (int q = 0; q < 4; q++) sacc[j][q] = 0.f;
        #pragma unroll
        for (int ks = 0; ks < 4; ks++) {
            #pragma unroll
            for (int ng = 0; ng < 4; ng++) {
                uint32_t kh[4], kl[4];
                int row = ng*16 + kb_r;
                int cb  = (ks*16 + kb_c) * 2;
                ldm4(kh, swz128(stage + 0*ATILE_B, row, cb));
                ldm4(kl, swz128(stage + 1*ATILE_B, row, cb));
                mma16816(sacc[2*ng+0], Qh[ks], kh + 0);
                mma16816(sacc[2*ng+1], Qh[ks], kh + 2);
                mma16816(sacc[2*ng+0], Ql[ks], kh + 0);
                mma16816(sacc[2*ng+1], Ql[ks], kh + 2);
                mma16816(sacc[2*ng+0], Qh[ks], kl + 0);
                mma16816(sacc[2*ng+1], Qh[ks], kl + 2);
            }
        }
        const float scale = 0.03125f;
        #pragma unroll
        for (int j = 0; j < 8; j++)
            #pragma unroll
            for (int q = 0; q < 4; q++) sacc[j][q] *= scale;
        if (kbkey + 63 > wrow) {
            #pragma unroll
            for (int j = 0; j < 8; j++) {
                int c0 = kbkey + j*8 + tc2;
                if (c0     > gr0) sacc[j][0] = -1e30f;
                if (c0 + 1 > gr0) sacc[j][1] = -1e30f;
                if (c0     > gr1) sacc[j][2] = -1e30f;
                if (c0 + 1 > gr1) sacc[j][3] = -1e30f;
            }
        }
        float mt0 = -1e30f, mt1 = -1e30f;
        #pragma unroll
        for (int j = 0; j < 8; j++) {
            mt0 = fmaxf(mt0, fmaxf(sacc[j][0], sacc[j][1]));
            mt1 = fmaxf(mt1, fmaxf(sacc[j][2], sacc[j][3]));
        }
        mt0 = fmaxf(mt0, __shfl_xor_sync(0xffffffffu, mt0, 1));
        mt0 = fmaxf(mt0, __shfl_xor_sync(0xffffffffu, mt0, 2));
        mt1 = fmaxf(mt1, __shfl_xor_sync(0xffffffffu, mt1, 1));
        mt1 = fmaxf(mt1, __shfl_xor_sync(0xffffffffu, mt1, 2));
        float mn0 = fmaxf(m0, mt0), mn1 = fmaxf(m1, mt1);
        float f0 = __expf(m0 - mn0), f1 = __expf(m1 - mn1);
        float rs0 = 0.f, rs1 = 0.f;
        #pragma unroll
        for (int j = 0; j < 8; j++) {
            sacc[j][0] = __expf(sacc[j][0] - mn0);
            sacc[j][1] = __expf(sacc[j][1] - mn0);
            sacc[j][2] = __expf(sacc[j][2] - mn1);
            sacc[j][3] = __expf(sacc[j][3] - mn1);
            rs0 += sacc[j][0] + sacc[j][1];
            rs1 += sacc[j][2] + sacc[j][3];
        }
        rs0 += __shfl_xor_sync(0xffffffffu, rs0, 1);
        rs0 += __shfl_xor_sync(0xffffffffu, rs0, 2);
        rs1 += __shfl_xor_sync(0xffffffffu, rs1, 1);
        rs1 += __shfl_xor_sync(0xffffffffu, rs1, 2);
        l0 = l0 * f0 + rs0;  l1 = l1 * f1 + rs1;
        m0 = mn0;  m1 = mn1;
        #pragma unroll
        for (int j = 0; j < 8; j++) {
            oacc[j][0] *= f0; oacc[j][1] *= f0;
            oacc[j][2] *= f1; oacc[j][3] *= f1;
        }
        #pragma unroll
        for (int ks = 0; ks < 4; ks++) {
            uint32_t pfr[4];
            pfr[0] = pack_bf16(sacc[2*ks  ][0], sacc[2*ks  ][1]);
            pfr[1] = pack_bf16(sacc[2*ks  ][2], sacc[2*ks  ][3]);
            pfr[2] = pack_bf16(sacc[2*ks+1][0], sacc[2*ks+1][1]);
            pfr[3] = pack_bf16(sacc[2*ks+1][2], sacc[2*ks+1][3]);
            #pragma unroll
            for (int nd = 0; nd < 4; nd++) {
                uint32_t vh[4], vl[4];
                int row = ks*16 + vb_r;
                int cb  = (nd*16 + vb_c) * 2;
                ldm4t(vh, swz128(stage + 2*ATILE_B, row, cb));
                ldm4t(vl, swz128(stage + 3*ATILE_B, row, cb));
                mma16816(oacc[2*nd+0], pfr, vh + 0);
                mma16816(oacc[2*nd+1], pfr, vh + 2);
                mma16816(oacc[2*nd+0], pfr, vl + 0);
                mma16816(oacc[2*nd+1], pfr, vl + 2);
            }
        }
    }

    float rl0 = 1.0f / l0, rl1 = 1.0f / l1;
    size_t ob0 = ((size_t)b * TT + gr0) * DD + h * 64;
    size_t ob1 = ((size_t)b * TT + gr1) * DD + h * 64;
    #pragma unroll
    for (int jd = 0; jd < 8; jd++) {
        uint32_t hp, lp;
        split2(oacc[jd][0] * rl0, oacc[jd][1] * rl0, hp, lp);
        *(uint32_t*)(oh + ob0 + jd*8 + tc2) = hp;
        *(uint32_t*)(ol + ob0 + jd*8 + tc2) = lp;
        split2(oacc[jd][2] * rl1, oacc[jd][3] * rl1, hp, lp);
        *(uint32_t*)(oh + ob1 + jd*8 + tc2) = hp;
        *(uint32_t*)(ol + ob1 + jd*8 + tc2) = lp;
    }
}

// ---------------- launch ------------------------------------------------------
extern "C" void kernel_launch(void* const* d_in, const int* in_sizes, int n_in,
                              void* d_out, int out_size) {
    const float* x   = (const float*)d_in[0];
    const float* Wq  = (const float*)d_in[1];
    const float* Wk  = (const float*)d_in[2];
    const float* Wv  = (const float*)d_in[3];
    const float* Wp  = (const float*)d_in[4];
    const float* bp  = (const float*)d_in[5];
    const float* W1  = (const float*)d_in[6];
    const float* b1  = (const float*)d_in[7];
    const float* W2  = (const float*)d_in[8];
    const float* b2  = (const float*)d_in[9];
    const float* g1  = (const float*)d_in[10];
    const float* be1 = (const float*)d_in[11];
    const float* g2  = (const float*)d_in[12];
    const float* be2 = (const float*)d_in[13];
    float* out = (float*)d_out;

    bf16 *hh, *hl, *oh, *ol, *x2h, *x2l, *h2h, *h2l, *mdh, *mdl, *qkvh, *qkvl;
    cudaGetSymbolAddress((void**)&hh,  g_hh);  cudaGetSymbolAddress((void**)&hl,  g_hl);
    cudaGetSymbolAddress((void**)&oh,  g_oh);  cudaGetSymbolAddress((void**)&ol,  g_ol);
    cudaGetSymbolAddress((void**)&x2h, g_x2h); cudaGetSymbolAddress((void**)&x2l, g_x2l);
    cudaGetSymbolAddress((void**)&h2h, g_h2h); cudaGetSymbolAddress((void**)&h2l, g_h2l);
    cudaGetSymbolAddress((void**)&mdh, g_mdh); cudaGetSymbolAddress((void**)&mdl, g_mdl);
    cudaGetSymbolAddress((void**)&qkvh, g_qkv_h); cudaGetSymbolAddress((void**)&qkvl, g_qkv_l);
    bf16 *Wqkv_h, *Wqkv_l;
    cudaGetSymbolAddress((void**)&Wqkv_h, g_Wqkv_h);
    cudaGetSymbolAddress((void**)&Wqkv_l, g_Wqkv_l);
    bf16 *Wp_h, *Wp_l, *W1_h, *W1_l, *W2_h, *W2_l;
    cudaGetSymbolAddress((void**)&Wp_h, g_Wp_h);
    cudaGetSymbolAddress((void**)&Wp_l, g_Wp_l);
    cudaGetSymbolAddress((void**)&W1_h, g_W1_h);
    cudaGetSymbolAddress((void**)&W1_l, g_W1_l);
    cudaGetSymbolAddress((void**)&W2_h, g_W2_h);
    cudaGetSymbolAddress((void**)&W2_l, g_W2_l);

    cudaFuncSetAttribute(attn_tc,
                         cudaFuncAttributeMaxDynamicSharedMemorySize, ATTN_SMEM3);
    cudaFuncSetAttribute(gemm_tc<false,true>,
                         cudaFuncAttributeMaxDynamicSharedMemorySize, GEMM_SMEM);
    cudaFuncSetAttribute(gemm_tc<true,true>,
                         cudaFuncAttributeMaxDynamicSharedMemorySize, GEMM_SMEM);
    cudaFuncSetAttribute(gemm_tc<false,false>,
                         cudaFuncAttributeMaxDynamicSharedMemorySize, GEMM_SMEM);

    dim3 tb(32, 8);
    prep_qkv<<<dim3(2, 32, 48), tb>>>(Wq, Wk, Wv, Wqkv_h, Wqkv_l);
    prep_all<<<9216, tb>>>(Wp, W1, W2);

    // LN1 (fp32 in, pair out)
    ln_kernel<false><<<MROWS, 256>>>(x, nullptr, nullptr, g1, be1, hh, hl);
    // QKV GEMM -> qkv pair
    gemm_tc<false,true><<<dim3(D3/128, MROWS/128), 256, GEMM_SMEM>>>(
        hh, hl, Wqkv_h, Wqkv_l, nullptr, nullptr, nullptr,
        nullptr, qkvh, qkvl, MROWS, D3, DD);
    // attention -> o pair
    attn_tc<<<dim3(TT/128, BB*HH), 256, ATTN_SMEM3>>>(qkvh, qkvl, oh, ol);
    // proj + bias + residual(h) -> x2 pair
    gemm_tc<false,true><<<dim3(DD/128, MROWS/128), 256, GEMM_SMEM>>>(
        oh, ol, Wp_h, Wp_l, bp, hh, hl,
        nullptr, x2h, x2l, MROWS, DD, DD);
    // LN2 (pair in, pair out)
    ln_kernel<true><<<MROWS, 256>>>(nullptr, x2h, x2l, g2, be2, h2h, h2l);
    // FFN1 + bias + relu -> mid pair
    gemm_tc<true,true><<<dim3(D4/128, MROWS/128), 256, GEMM_SMEM>>>(
        h2h, h2l, W1_h, W1_l, b1, nullptr, nullptr,
        nullptr, mdh, mdl, MROWS, D4, DD);
    // FFN2 + bias + residual(h2) -> fp32 out
    gemm_tc<false,false><<<dim3(DD/128, MROWS/128), 256, GEMM_SMEM>>>(
        mdh, mdl, W2_h, W2_l, b2, h2h, h2l,
        out, nullptr, nullptr, MROWS, DD, D4);
}